// round 12
// baseline (speedup 1.0000x reference)
#include <cuda_runtime.h>
#include <cstdint>
#include <cstddef>

#define NB   4
#define LEN  2000
#define LP   2048
#define KDIM 512
#define HDIM 256
#define SK   36                       // smem row stride (32 k + 4 pad) -> conflict-free
#define STAGE_F (128 * SK)            // floats per matrix per stage (fc kernel)
#define SMEM_BYTES (4 * STAGE_F * 4)  // fc kernel: 2 mats x 2 stages = 73728 B

// fused att+softmax kernel smem layout (floats)
#define AT_BSTR 516                   // B panel row stride (512 + 4) -> conflict-free
#define AT_B_F  (64 * AT_BSTR)        // 33024
#define AT_A_F  (128 * SK)            // 4608 per stage
#define AT_OFF_A0  AT_B_F
#define AT_OFF_A1  (AT_B_F + AT_A_F)
#define AT_OFF_RM  (AT_B_F + 2 * AT_A_F)          // 2 x 128
#define AT_OFF_MG  (AT_OFF_RM + 256)              // 3 x 4 x 64
#define AT_SMEM_BYTES ((AT_OFF_MG + 768) * 4)     // 173056 B

// ---------------- scratch (static device globals; no runtime alloc) ----------------
__device__ float g_scale[2];
__device__ float g_P1 [(size_t)NB * LP * KDIM];    // fc(X,Q)*h   (pad rows = 0)
__device__ float g_A1Y[(size_t)NB * LP * KDIM];    // fc(Y,K)
__device__ float g_P2 [(size_t)NB * LP * KDIM];    // fc(Y,Q)*h
__device__ float g_A2X[(size_t)NB * LP * KDIM];    // fc(X,K)
__device__ float g_w1 [NB * LEN];
__device__ float g_w2 [NB * LEN];
__device__ float g_part[8 * NB * KDIM];

// ---------------- helpers ----------------
__device__ __forceinline__ unsigned f2tf(float f) {
    unsigned u;
    asm("cvt.rna.tf32.f32 %0, %1;" : "=r"(u) : "f"(f));
    return u;
}
__device__ __forceinline__ float4 cvt4(float4 v) {
    return make_float4(__uint_as_float(f2tf(v.x)), __uint_as_float(f2tf(v.y)),
                       __uint_as_float(f2tf(v.z)), __uint_as_float(f2tf(v.w)));
}
__device__ __forceinline__ void mma_tf32(float* c, const unsigned* a, const unsigned* b) {
    asm volatile(
        "mma.sync.aligned.m16n8k8.row.col.f32.tf32.tf32.f32 "
        "{%0,%1,%2,%3}, {%4,%5,%6,%7}, {%8,%9}, {%0,%1,%2,%3};\n"
        : "+f"(c[0]), "+f"(c[1]), "+f"(c[2]), "+f"(c[3])
        : "r"(a[0]), "r"(a[1]), "r"(a[2]), "r"(a[3]), "r"(b[0]), "r"(b[1]));
}

// warp compute over one 32-K smem stage (fc kernel): warp = 64x32
__device__ __forceinline__ void warp_compute(const float* As, const float* Bs,
                                             int wm, int wn, int lane,
                                             float acc[4][4][4])
{
#pragma unroll
    for (int ks = 0; ks < 4; ks++) {
        unsigned af[4][4], bf[4][2];
#pragma unroll
        for (int mf = 0; mf < 4; mf++) {
            const float* p = &As[(wm * 64 + mf * 16 + (lane >> 2)) * SK + ks * 8 + (lane & 3)];
            af[mf][0] = __float_as_uint(p[0]);
            af[mf][1] = __float_as_uint(p[8 * SK]);
            af[mf][2] = __float_as_uint(p[4]);
            af[mf][3] = __float_as_uint(p[8 * SK + 4]);
        }
#pragma unroll
        for (int nf = 0; nf < 4; nf++) {
            const float* p = &Bs[(wn * 32 + nf * 8 + (lane >> 2)) * SK + ks * 8 + (lane & 3)];
            bf[nf][0] = __float_as_uint(p[0]);
            bf[nf][1] = __float_as_uint(p[4]);
        }
#pragma unroll
        for (int mf = 0; mf < 4; mf++)
#pragma unroll
            for (int nf = 0; nf < 4; nf++)
                mma_tf32(acc[mf][nf], af[mf], bf[nf]);
    }
}

// ---------------- kernel 1: weight-norm scales ----------------
__global__ void norm_kernel(const float* __restrict__ Qv, const float* __restrict__ Qg,
                            const float* __restrict__ Kv, const float* __restrict__ Kg)
{
    const float* V = blockIdx.x ? Kv : Qv;
    const float* G = blockIdx.x ? Kg : Qg;
    __shared__ float red[256];
    float s = 0.f;
    for (int i = threadIdx.x; i < KDIM * HDIM; i += 256) {
        float v = V[i];
        s += v * v;
    }
    red[threadIdx.x] = s;
    __syncthreads();
    for (int st = 128; st > 0; st >>= 1) {
        if (threadIdx.x < st) red[threadIdx.x] += red[threadIdx.x + st];
        __syncthreads();
    }
    if (threadIdx.x == 0) g_scale[blockIdx.x] = G[0] / sqrtf(red[0]);
}

// ---------------- kernel 2: all 4 FC projections fused (blockIdx.z selects) ----------------
__global__ __launch_bounds__(256, 2) void fc_mma(
    const float* __restrict__ X, const float* __restrict__ Y,
    const float* __restrict__ Qv, const float* __restrict__ Kv,
    const float* __restrict__ Qb, const float* __restrict__ Kb,
    const float* __restrict__ hvec)
{
    const int z = blockIdx.z;
    const bool qSide = (z == 0) || (z == 2);
    const float* Xin  = (z == 0 || z == 3) ? X : Y;
    const float* W    = qSide ? Qv : Kv;
    const float* bias = qSide ? Qb : Kb;
    float* out = (z == 0) ? g_P1 : (z == 1) ? g_A1Y : (z == 2) ? g_P2 : g_A2X;

    extern __shared__ float sh[];
    float* AsB = sh;
    float* BsB = sh + 2 * STAGE_F;

    const int tid  = threadIdx.x;
    const int lane = tid & 31;
    const int warp = tid >> 5;
    const int wm = warp >> 2, wn = warp & 3;
    const int rowBase = blockIdx.y * 128;
    const int colBase = blockIdx.x * 128;
    const int r  = tid >> 1;
    const int kc = (tid & 1) << 2;

    const int  m  = rowBase + r;
    const int  bb = m >> 11;
    const int  ll = m & (LP - 1);
    const bool avalid = ll < LEN;
    const float* Aptr = Xin + ((size_t)bb * LEN + ll) * HDIM + kc;
    const float* Bptr = W + (size_t)(colBase + r) * HDIM + kc;

    float acc[4][4][4];
#pragma unroll
    for (int i = 0; i < 4; i++)
#pragma unroll
        for (int j = 0; j < 4; j++)
#pragma unroll
            for (int t = 0; t < 4; t++) acc[i][j][t] = 0.f;

    float4 pa[4], pb[4];
#pragma unroll
    for (int j = 0; j < 4; j++) {
        pa[j] = avalid ? *(const float4*)(Aptr + j * 8) : make_float4(0.f, 0.f, 0.f, 0.f);
        pb[j] = *(const float4*)(Bptr + j * 8);
    }
#pragma unroll
    for (int j = 0; j < 4; j++) {
        *(float4*)&AsB[r * SK + kc + j * 8] = cvt4(pa[j]);
        *(float4*)&BsB[r * SK + kc + j * 8] = cvt4(pb[j]);
    }
    __syncthreads();

    const int NCH = HDIM / 32;
    int buf = 0;
    for (int ch = 0; ch < NCH; ch++) {
        if (ch + 1 < NCH) {
            int koff = (ch + 1) * 32;
#pragma unroll
            for (int j = 0; j < 4; j++) {
                pa[j] = avalid ? *(const float4*)(Aptr + koff + j * 8)
                               : make_float4(0.f, 0.f, 0.f, 0.f);
                pb[j] = *(const float4*)(Bptr + koff + j * 8);
            }
        }
        warp_compute(AsB + buf * STAGE_F, BsB + buf * STAGE_F, wm, wn, lane, acc);
        if (ch + 1 < NCH) {
            int nb = buf ^ 1;
#pragma unroll
            for (int j = 0; j < 4; j++) {
                *(float4*)&AsB[nb * STAGE_F + r * SK + kc + j * 8] = cvt4(pa[j]);
                *(float4*)&BsB[nb * STAGE_F + r * SK + kc + j * 8] = cvt4(pb[j]);
            }
        }
        __syncthreads();
        buf ^= 1;
    }

    const float scale = g_scale[qSide ? 0 : 1];
#pragma unroll
    for (int mf = 0; mf < 4; mf++) {
        int row0 = rowBase + wm * 64 + mf * 16 + (lane >> 2);
        int row1 = row0 + 8;
        bool v0 = (row0 & (LP - 1)) < LEN;
        bool v1 = (row1 & (LP - 1)) < LEN;
#pragma unroll
        for (int nf = 0; nf < 4; nf++) {
            int col = colBase + wn * 32 + nf * 8 + (lane & 3) * 2;
            float b0 = bias[col], b1 = bias[col + 1];
            float h0 = qSide ? hvec[col] : 1.f, h1 = qSide ? hvec[col + 1] : 1.f;
            float* c = acc[mf][nf];
            float2 o0 = make_float2(
                v0 ? fmaxf(scale * c[0] + b0, 0.f) * h0 : 0.f,
                v0 ? fmaxf(scale * c[1] + b1, 0.f) * h1 : 0.f);
            float2 o1 = make_float2(
                v1 ? fmaxf(scale * c[2] + b0, 0.f) * h0 : 0.f,
                v1 ? fmaxf(scale * c[3] + b1, 0.f) * h1 : 0.f);
            *(float2*)&out[(size_t)row0 * KDIM + col] = o0;
            *(float2*)&out[(size_t)row1 * KDIM + col] = o1;
        }
    }
}

// ---------------- kernel 3: FUSED Gram-GEMM + per-column online softmax ----------------
// grid: (LP/64, NB, 2).  CTA owns 64 softmax columns; iterates 16 row tiles of 128.
// mat0: logits A1[v,q] = P1[v,:]·A1Y[q,:], softmax over v weighted by mask1, outer mask2 -> w1
// mat1: logits A2[q,v] = P2[q,:]·A2X[v,:], softmax over q weighted by mask2, outer mask1 -> w2
// hb omitted: softmax is shift-invariant; pad rows excluded via validity predicate;
// pad columns (>=LEN) computed but never written.
__global__ __launch_bounds__(256, 1) void att_soft(
    const float* __restrict__ mask1, const float* __restrict__ mask2)
{
    const int sel = blockIdx.z;
    const int b   = blockIdx.y;
    const float* Ag    = (sel ? g_P2  : g_P1)  + (size_t)b * LP * KDIM;
    const float* Bg    = (sel ? g_A2X : g_A1Y) + (size_t)b * LP * KDIM;
    const float* rmask = sel ? mask2 : mask1;
    const float* cmask = sel ? mask1 : mask2;
    float*       wout  = sel ? g_w2  : g_w1;

    extern __shared__ float sh[];
    float* Bsm = sh;                 // persistent 64 x 512 tf32, stride 516
    float* rmS = sh + AT_OFF_RM;     // 2 x 128 row-mask tiles
    float* mgM = sh + AT_OFF_MG;     // 4 x 64 merge scratch (m)
    float* mgD = mgM + 256;          // 4 x 64 (den)
    float* mgN = mgD + 256;          // 4 x 64 (num)

    const int tid  = threadIdx.x;
    const int lane = tid & 31;
    const int warp = tid >> 5;
    const int wm = warp >> 1;        // 4 m-warps (32 rows each)
    const int wn = warp & 1;         // 2 n-warps (32 cols each)
    const int lq4 = lane >> 2;
    const int colBase = blockIdx.x * 64;
    const int r  = tid >> 1;
    const int kc = (tid & 1) << 2;

    // ---- prologue: persistent B panel + first A chunk ----
    {
        const int brow = tid >> 2;
        const int bkc  = (tid & 3) * 4;
        const float* bp = Bg + (size_t)(colBase + brow) * KDIM + bkc;
        float* bs = Bsm + brow * AT_BSTR + bkc;
#pragma unroll
        for (int j = 0; j < 32; j++)
            *(float4*)(bs + j * 16) = cvt4(*(const float4*)(bp + j * 16));

        const float* ap = Ag + (size_t)r * KDIM + kc;
#pragma unroll
        for (int j = 0; j < 4; j++)
            *(float4*)&sh[AT_OFF_A0 + r * SK + kc + j * 8] = cvt4(*(const float4*)(ap + j * 8));
    }
    __syncthreads();

    float acc[2][4][4];
#pragma unroll
    for (int i = 0; i < 2; i++)
#pragma unroll
        for (int j = 0; j < 4; j++)
#pragma unroll
            for (int t = 0; t < 4; t++) acc[i][j][t] = 0.f;

    float mS[8], dS[8], nS[8];
#pragma unroll
    for (int s = 0; s < 8; s++) { mS[s] = -1e30f; dS[s] = 0.f; nS[s] = 0.f; }

    int buf = 0;
    for (int step = 0; step < 256; step++) {
        const int vt = step >> 4;
        const int ch = step & 15;

        // prefetch next A chunk
        float4 pa[4];
        const bool more = (step + 1 < 256);
        if (more) {
            const int nvt = (step + 1) >> 4, nch = (step + 1) & 15;
            const float* ap = Ag + (size_t)(nvt * 128 + r) * KDIM + nch * 32 + kc;
#pragma unroll
            for (int j = 0; j < 4; j++) pa[j] = *(const float4*)(ap + j * 8);
        }

        // compute: A chunk (smem buf) x persistent B at k-offset ch*32
        {
            const float* As = sh + (buf ? AT_OFF_A1 : AT_OFF_A0);
            const int koff = ch * 32;
#pragma unroll
            for (int ks = 0; ks < 4; ks++) {
                unsigned af[2][4], bf[4][2];
#pragma unroll
                for (int mf = 0; mf < 2; mf++) {
                    const float* p = &As[(wm * 32 + mf * 16 + lq4) * SK + ks * 8 + (lane & 3)];
                    af[mf][0] = __float_as_uint(p[0]);
                    af[mf][1] = __float_as_uint(p[8 * SK]);
                    af[mf][2] = __float_as_uint(p[4]);
                    af[mf][3] = __float_as_uint(p[8 * SK + 4]);
                }
#pragma unroll
                for (int nf = 0; nf < 4; nf++) {
                    const float* p = &Bsm[(wn * 32 + nf * 8 + lq4) * AT_BSTR + koff + ks * 8 + (lane & 3)];
                    bf[nf][0] = __float_as_uint(p[0]);
                    bf[nf][1] = __float_as_uint(p[4]);
                }
#pragma unroll
                for (int mf = 0; mf < 2; mf++)
#pragma unroll
                    for (int nf = 0; nf < 4; nf++)
                        mma_tf32(acc[mf][nf], af[mf], bf[nf]);
            }
        }

        // store prefetched A chunk into other buffer
        if (more) {
            float* dst = sh + (buf ? AT_OFF_A0 : AT_OFF_A1);
#pragma unroll
            for (int j = 0; j < 4; j++)
                *(float4*)&dst[r * SK + kc + j * 8] = cvt4(pa[j]);
        }

        // load row-mask tile for current vt (consumed at epilogue of step 16vt+15)
        if (ch == 0 && tid < 128) {
            const int row = vt * 128 + tid;
            rmS[(vt & 1) * 128 + tid] = (row < LEN) ? rmask[b * LEN + row] : 0.f;
        }
        __syncthreads();
        buf ^= 1;

        // ---- tile epilogue: online softmax update over this tile's 128 rows ----
        if (ch == 15) {
            const float* rm = rmS + (vt & 1) * 128;
            const int rbase = vt * 128 + wm * 32 + lq4;
            const float v0 = (rbase      < LEN) ? 1.f : 0.f;
            const float v1 = (rbase + 8  < LEN) ? 1.f : 0.f;
            const float v2 = (rbase + 16 < LEN) ? 1.f : 0.f;
            const float v3 = (rbase + 24 < LEN) ? 1.f : 0.f;
            const float w0 = rm[wm * 32 + lq4];
            const float w1 = rm[wm * 32 + lq4 + 8];
            const float w2 = rm[wm * 32 + lq4 + 16];
            const float w3 = rm[wm * 32 + lq4 + 24];
#pragma unroll
            for (int nf = 0; nf < 4; nf++)
#pragma unroll
                for (int p = 0; p < 2; p++) {
                    const int s = nf * 2 + p;
                    const float x0 = acc[0][nf][p];
                    const float x1 = acc[0][nf][2 + p];
                    const float x2 = acc[1][nf][p];
                    const float x3 = acc[1][nf][2 + p];
                    const float nm = fmaxf(mS[s],
                        fmaxf(fmaxf(x0, x1), fmaxf(x2, x3)));
                    const float sc = __expf(mS[s] - nm);
                    const float e0 = v0 * __expf(x0 - nm);
                    const float e1 = v1 * __expf(x1 - nm);
                    const float e2 = v2 * __expf(x2 - nm);
                    const float e3 = v3 * __expf(x3 - nm);
                    dS[s] = dS[s] * sc + (e0 + e1 + e2 + e3);
                    nS[s] = nS[s] * sc + (w0 * e0 + w1 * e1 + w2 * e2 + w3 * e3);
                    mS[s] = nm;
                }
#pragma unroll
            for (int i = 0; i < 2; i++)
#pragma unroll
                for (int j = 0; j < 4; j++)
#pragma unroll
                    for (int t = 0; t < 4; t++) acc[i][j][t] = 0.f;
        }
    }

    // ---- final merge: shfl across row-groups, smem across m-warps ----
#pragma unroll
    for (int s = 0; s < 8; s++) {
#pragma unroll
        for (int d = 4; d <= 16; d <<= 1) {
            const float mo = __shfl_xor_sync(0xffffffffu, mS[s], d);
            const float doo = __shfl_xor_sync(0xffffffffu, dS[s], d);
            const float no = __shfl_xor_sync(0xffffffffu, nS[s], d);
            const float nm = fmaxf(mS[s], mo);
            const float s1 = __expf(mS[s] - nm), s2 = __expf(mo - nm);
            dS[s] = dS[s] * s1 + doo * s2;
            nS[s] = nS[s] * s1 + no * s2;
            mS[s] = nm;
        }
    }
    if (lane < 4) {
#pragma unroll
        for (int nf = 0; nf < 4; nf++)
#pragma unroll
            for (int p = 0; p < 2; p++) {
                const int s = nf * 2 + p;
                const int clo = wn * 32 + nf * 8 + lane * 2 + p;
                mgM[wm * 64 + clo] = mS[s];
                mgD[wm * 64 + clo] = dS[s];
                mgN[wm * 64 + clo] = nS[s];
            }
    }
    __syncthreads();
    if (tid < 64) {
        float M = mgM[tid], D = mgD[tid], N = mgN[tid];
#pragma unroll
        for (int w = 1; w < 4; w++) {
            const float mo = mgM[w * 64 + tid];
            const float nm = fmaxf(M, mo);
            const float s1 = __expf(M - nm), s2 = __expf(mo - nm);
            D = D * s1 + mgD[w * 64 + tid] * s2;
            N = N * s1 + mgN[w * 64 + tid] * s2;
            M = nm;
        }
        const int col = colBase + tid;
        if (col < LEN)
            wout[b * LEN + col] = cmask[b * LEN + col] * N / D;
    }
}

// ---------------- kernel 5: pooled partial GEMVs ----------------
__global__ void pooled_partial()
{
    const int b = blockIdx.y, sp = blockIdx.z;
    const int k = blockIdx.x * 128 + threadIdx.x;
    const int q0 = sp * (LEN / 8), q1 = q0 + (LEN / 8);
    const float* P = g_A1Y + (size_t)b * LP * KDIM;
    const float* Q = g_A2X + (size_t)b * LP * KDIM;
    float acc = 0.f;
    for (int q = q0; q < q1; q++) acc = fmaf(g_w1[b * LEN + q], P[(size_t)q * KDIM + k], acc);
    for (int q = q0; q < q1; q++) acc = fmaf(g_w2[b * LEN + q], Q[(size_t)q * KDIM + k], acc);
    g_part[(sp * NB + b) * KDIM + k] = acc;
}

// ---------------- kernel 6: batch layernorm over B=4 ----------------
__global__ void ln_kernel(const float* __restrict__ gamma, const float* __restrict__ beta,
                          float* __restrict__ out)
{
    const int k = blockIdx.x * 256 + threadIdx.x;
    float p[NB];
#pragma unroll
    for (int b = 0; b < NB; b++) {
        float s = 0.f;
#pragma unroll
        for (int sp = 0; sp < 8; sp++) s += g_part[(sp * NB + b) * KDIM + k];
        p[b] = s * (1.0f / LEN);
    }
    float mu = 0.25f * (p[0] + p[1] + p[2] + p[3]);
    float var = 0.f;
#pragma unroll
    for (int b = 0; b < NB; b++) { float d = p[b] - mu; var += d * d; }
    var *= 0.25f;
    float inv = rsqrtf(var + 1e-5f);
#pragma unroll
    for (int b = 0; b < NB; b++)
        out[b * KDIM + k] = gamma[k] * (p[b] - mu) * inv + beta[k];
}

// ---------------- launch ----------------
extern "C" void kernel_launch(void* const* d_in, const int* in_sizes, int n_in,
                              void* d_out, int out_size)
{
    const float* X      = (const float*)d_in[0];
    const float* Y      = (const float*)d_in[1];
    const float* mask1  = (const float*)d_in[2];
    const float* mask2  = (const float*)d_in[3];
    const float* Qv     = (const float*)d_in[4];
    const float* Qg     = (const float*)d_in[5];
    const float* Qb     = (const float*)d_in[6];
    const float* Kv     = (const float*)d_in[7];
    const float* Kg     = (const float*)d_in[8];
    const float* Kb     = (const float*)d_in[9];
    const float* h_mat  = (const float*)d_in[10];
    const float* gamma  = (const float*)d_in[12];
    const float* beta   = (const float*)d_in[13];
    float* out = (float*)d_out;

    static bool attr_done = false;
    if (!attr_done) {
        cudaFuncSetAttribute(fc_mma,   cudaFuncAttributeMaxDynamicSharedMemorySize, SMEM_BYTES);
        cudaFuncSetAttribute(att_soft, cudaFuncAttributeMaxDynamicSharedMemorySize, AT_SMEM_BYTES);
        attr_done = true;
    }

    norm_kernel<<<2, 256>>>(Qv, Qg, Kv, Kg);

    dim3 fcGrid(KDIM / 128, (NB * LP) / 128, 4);
    fc_mma<<<fcGrid, 256, SMEM_BYTES>>>(X, Y, Qv, Kv, Qb, Kb, h_mat);

    dim3 atGrid(LP / 64, NB, 2);
    att_soft<<<atGrid, 256, AT_SMEM_BYTES>>>(mask1, mask2);

    pooled_partial<<<dim3(KDIM / 128, NB, 8), 128>>>();
    ln_kernel<<<KDIM / 256, 256>>>(gamma, beta, out);
}

// round 15
// speedup vs baseline: 1.2701x; 1.2701x over previous
#include <cuda_runtime.h>
#include <cstdint>
#include <cstddef>

#define NB   4
#define LEN  2000
#define LP   2048
#define KDIM 512
#define HDIM 256
#define SK   36                       // smem row stride (32 k + 4 pad) -> conflict-free
#define STAGE_F (128 * SK)            // floats per matrix per stage
#define SMEM_BYTES (4 * STAGE_F * 4)  // 2 matrices x 2 stages x STAGE_F x 4B = 73728
#define QSPLIT 64                     // pooled q-splits

// ---------------- scratch (static device globals; no runtime alloc) ----------------
__device__ float g_scale[2];
__device__ float g_P1 [(size_t)NB * LP * KDIM];    // fc(X,Q)*h   (pad rows = 0)
__device__ float g_A1Y[(size_t)NB * LP * KDIM];    // fc(Y,K)
__device__ float g_P2 [(size_t)NB * LP * KDIM];    // fc(Y,Q)*h
__device__ float g_A2X[(size_t)NB * LP * KDIM];    // fc(X,K)
__device__ float g_A1 [(size_t)NB * LP * LP];      // A1[b,v,q]
__device__ float g_A2 [(size_t)NB * LP * LP];      // A2[b,q,v]
__device__ float g_w1 [NB * LEN];
__device__ float g_w2 [NB * LEN];
__device__ float g_redM[8 * NB * LP];              // [mat*4+part][b][LP] partial softmax triples
__device__ float g_redD[8 * NB * LP];
__device__ float g_redN[8 * NB * LP];
__device__ float g_part[QSPLIT * NB * KDIM];       // pooled partial sums

// ---------------- helpers ----------------
__device__ __forceinline__ unsigned f2tf(float f) {
    unsigned u;
    asm("cvt.rna.tf32.f32 %0, %1;" : "=r"(u) : "f"(f));
    return u;
}
__device__ __forceinline__ float4 cvt4(float4 v) {
    return make_float4(__uint_as_float(f2tf(v.x)), __uint_as_float(f2tf(v.y)),
                       __uint_as_float(f2tf(v.z)), __uint_as_float(f2tf(v.w)));
}
__device__ __forceinline__ void mma_tf32(float* c, const unsigned* a, const unsigned* b) {
    asm volatile(
        "mma.sync.aligned.m16n8k8.row.col.f32.tf32.tf32.f32 "
        "{%0,%1,%2,%3}, {%4,%5,%6,%7}, {%8,%9}, {%0,%1,%2,%3};\n"
        : "+f"(c[0]), "+f"(c[1]), "+f"(c[2]), "+f"(c[3])
        : "r"(a[0]), "r"(a[1]), "r"(a[2]), "r"(a[3]), "r"(b[0]), "r"(b[1]));
}

// warp compute over one 32-K smem stage: 4 ks-steps of 16 m16n8k8 MMAs
__device__ __forceinline__ void warp_compute(const float* As, const float* Bs,
                                             int wm, int wn, int lane,
                                             float acc[4][4][4])
{
#pragma unroll
    for (int ks = 0; ks < 4; ks++) {
        unsigned af[4][4], bf[4][2];
#pragma unroll
        for (int mf = 0; mf < 4; mf++) {
            const float* p = &As[(wm * 64 + mf * 16 + (lane >> 2)) * SK + ks * 8 + (lane & 3)];
            af[mf][0] = __float_as_uint(p[0]);
            af[mf][1] = __float_as_uint(p[8 * SK]);
            af[mf][2] = __float_as_uint(p[4]);
            af[mf][3] = __float_as_uint(p[8 * SK + 4]);
        }
#pragma unroll
        for (int nf = 0; nf < 4; nf++) {
            const float* p = &Bs[(wn * 32 + nf * 8 + (lane >> 2)) * SK + ks * 8 + (lane & 3)];
            bf[nf][0] = __float_as_uint(p[0]);
            bf[nf][1] = __float_as_uint(p[4]);
        }
#pragma unroll
        for (int mf = 0; mf < 4; mf++)
#pragma unroll
            for (int nf = 0; nf < 4; nf++)
                mma_tf32(acc[mf][nf], af[mf], bf[nf]);
    }
}

// ---------------- kernel 1: weight-norm scales ----------------
__global__ void norm_kernel(const float* __restrict__ Qv, const float* __restrict__ Qg,
                            const float* __restrict__ Kv, const float* __restrict__ Kg)
{
    const float* V = blockIdx.x ? Kv : Qv;
    const float* G = blockIdx.x ? Kg : Qg;
    __shared__ float red[256];
    float s = 0.f;
    for (int i = threadIdx.x; i < KDIM * HDIM; i += 256) {
        float v = V[i];
        s += v * v;
    }
    red[threadIdx.x] = s;
    __syncthreads();
    for (int st = 128; st > 0; st >>= 1) {
        if (threadIdx.x < st) red[threadIdx.x] += red[threadIdx.x + st];
        __syncthreads();
    }
    if (threadIdx.x == 0) g_scale[blockIdx.x] = G[0] / sqrtf(red[0]);
}

// ---------------- kernel 2: all 4 FC projections fused (blockIdx.z selects) ----------------
__global__ __launch_bounds__(256, 2) void fc_mma(
    const float* __restrict__ X, const float* __restrict__ Y,
    const float* __restrict__ Qv, const float* __restrict__ Kv,
    const float* __restrict__ Qb, const float* __restrict__ Kb,
    const float* __restrict__ hvec)
{
    const int z = blockIdx.z;
    const bool qSide = (z == 0) || (z == 2);
    const float* Xin  = (z == 0 || z == 3) ? X : Y;
    const float* W    = qSide ? Qv : Kv;
    const float* bias = qSide ? Qb : Kb;
    float* out = (z == 0) ? g_P1 : (z == 1) ? g_A1Y : (z == 2) ? g_P2 : g_A2X;

    extern __shared__ float sh[];
    float* AsB = sh;
    float* BsB = sh + 2 * STAGE_F;

    const int tid  = threadIdx.x;
    const int lane = tid & 31;
    const int warp = tid >> 5;
    const int wm = warp >> 2, wn = warp & 3;
    const int rowBase = blockIdx.y * 128;
    const int colBase = blockIdx.x * 128;
    const int r  = tid >> 1;
    const int kc = (tid & 1) << 2;

    const int  m  = rowBase + r;
    const int  bb = m >> 11;
    const int  ll = m & (LP - 1);
    const bool avalid = ll < LEN;
    const float* Aptr = Xin + ((size_t)bb * LEN + ll) * HDIM + kc;
    const float* Bptr = W + (size_t)(colBase + r) * HDIM + kc;

    float acc[4][4][4];
#pragma unroll
    for (int i = 0; i < 4; i++)
#pragma unroll
        for (int j = 0; j < 4; j++)
#pragma unroll
            for (int t = 0; t < 4; t++) acc[i][j][t] = 0.f;

    float4 pa[4], pb[4];
#pragma unroll
    for (int j = 0; j < 4; j++) {
        pa[j] = avalid ? *(const float4*)(Aptr + j * 8) : make_float4(0.f, 0.f, 0.f, 0.f);
        pb[j] = *(const float4*)(Bptr + j * 8);
    }
#pragma unroll
    for (int j = 0; j < 4; j++) {
        *(float4*)&AsB[r * SK + kc + j * 8] = cvt4(pa[j]);
        *(float4*)&BsB[r * SK + kc + j * 8] = cvt4(pb[j]);
    }
    __syncthreads();

    const int NCH = HDIM / 32;
    int buf = 0;
    for (int ch = 0; ch < NCH; ch++) {
        if (ch + 1 < NCH) {
            int koff = (ch + 1) * 32;
#pragma unroll
            for (int j = 0; j < 4; j++) {
                pa[j] = avalid ? *(const float4*)(Aptr + koff + j * 8)
                               : make_float4(0.f, 0.f, 0.f, 0.f);
                pb[j] = *(const float4*)(Bptr + koff + j * 8);
            }
        }
        warp_compute(AsB + buf * STAGE_F, BsB + buf * STAGE_F, wm, wn, lane, acc);
        if (ch + 1 < NCH) {
            int nb = buf ^ 1;
#pragma unroll
            for (int j = 0; j < 4; j++) {
                *(float4*)&AsB[nb * STAGE_F + r * SK + kc + j * 8] = cvt4(pa[j]);
                *(float4*)&BsB[nb * STAGE_F + r * SK + kc + j * 8] = cvt4(pb[j]);
            }
        }
        __syncthreads();
        buf ^= 1;
    }

    const float scale = g_scale[qSide ? 0 : 1];
#pragma unroll
    for (int mf = 0; mf < 4; mf++) {
        int row0 = rowBase + wm * 64 + mf * 16 + (lane >> 2);
        int row1 = row0 + 8;
        bool v0 = (row0 & (LP - 1)) < LEN;
        bool v1 = (row1 & (LP - 1)) < LEN;
#pragma unroll
        for (int nf = 0; nf < 4; nf++) {
            int col = colBase + wn * 32 + nf * 8 + (lane & 3) * 2;
            float b0 = bias[col], b1 = bias[col + 1];
            float h0 = qSide ? hvec[col] : 1.f, h1 = qSide ? hvec[col + 1] : 1.f;
            float* c = acc[mf][nf];
            float2 o0 = make_float2(
                v0 ? fmaxf(scale * c[0] + b0, 0.f) * h0 : 0.f,
                v0 ? fmaxf(scale * c[1] + b1, 0.f) * h1 : 0.f);
            float2 o1 = make_float2(
                v1 ? fmaxf(scale * c[2] + b0, 0.f) * h0 : 0.f,
                v1 ? fmaxf(scale * c[3] + b1, 0.f) * h1 : 0.f);
            *(float2*)&out[(size_t)row0 * KDIM + col] = o0;
            *(float2*)&out[(size_t)row1 * KDIM + col] = o1;
        }
    }
}

// ---------------- kernel 3: both attention Gram matrices fused ----------------
__global__ __launch_bounds__(256, 2) void att_mma(const float* __restrict__ hbias_p)
{
    const int sel = blockIdx.z & 1;
    const int bz  = blockIdx.z >> 1;
    const float* A  = (sel ? g_P2  : g_P1)  + (size_t)bz * LP * KDIM;
    const float* Bm = (sel ? g_A2X : g_A1Y) + (size_t)bz * LP * KDIM;
    float*       C  = (sel ? g_A2  : g_A1)  + (size_t)bz * LP * LP;

    extern __shared__ float sh[];
    float* AsB = sh;
    float* BsB = sh + 2 * STAGE_F;

    const int tid  = threadIdx.x;
    const int lane = tid & 31;
    const int warp = tid >> 5;
    const int wm = warp >> 2, wn = warp & 3;
    const int rowBase = blockIdx.y * 128;
    const int colBase = blockIdx.x * 128;
    const int r  = tid >> 1;
    const int kc = (tid & 1) << 2;

    const float* Aptr = A  + (size_t)(rowBase + r) * KDIM + kc;
    const float* Bptr = Bm + (size_t)(colBase + r) * KDIM + kc;

    float acc[4][4][4];
#pragma unroll
    for (int i = 0; i < 4; i++)
#pragma unroll
        for (int j = 0; j < 4; j++)
#pragma unroll
            for (int t = 0; t < 4; t++) acc[i][j][t] = 0.f;

    float4 pa[4], pb[4];
#pragma unroll
    for (int j = 0; j < 4; j++) {
        pa[j] = *(const float4*)(Aptr + j * 8);
        pb[j] = *(const float4*)(Bptr + j * 8);
    }
#pragma unroll
    for (int j = 0; j < 4; j++) {
        *(float4*)&AsB[r * SK + kc + j * 8] = cvt4(pa[j]);
        *(float4*)&BsB[r * SK + kc + j * 8] = cvt4(pb[j]);
    }
    __syncthreads();

    const int NCH = KDIM / 32;
    int buf = 0;
    for (int ch = 0; ch < NCH; ch++) {
        if (ch + 1 < NCH) {
            int koff = (ch + 1) * 32;
#pragma unroll
            for (int j = 0; j < 4; j++) {
                pa[j] = *(const float4*)(Aptr + koff + j * 8);
                pb[j] = *(const float4*)(Bptr + koff + j * 8);
            }
        }
        warp_compute(AsB + buf * STAGE_F, BsB + buf * STAGE_F, wm, wn, lane, acc);
        if (ch + 1 < NCH) {
            int nb = buf ^ 1;
#pragma unroll
            for (int j = 0; j < 4; j++) {
                *(float4*)&AsB[nb * STAGE_F + r * SK + kc + j * 8] = cvt4(pa[j]);
                *(float4*)&BsB[nb * STAGE_F + r * SK + kc + j * 8] = cvt4(pb[j]);
            }
        }
        __syncthreads();
        buf ^= 1;
    }

    const float hb = *hbias_p;
#pragma unroll
    for (int mf = 0; mf < 4; mf++) {
        int row0 = rowBase + wm * 64 + mf * 16 + (lane >> 2);
        int row1 = row0 + 8;
#pragma unroll
        for (int nf = 0; nf < 4; nf++) {
            int col = colBase + wn * 32 + nf * 8 + (lane & 3) * 2;
            float* c = acc[mf][nf];
            *(float2*)&C[(size_t)row0 * LP + col] = make_float2(c[0] + hb, c[1] + hb);
            *(float2*)&C[(size_t)row1 * LP + col] = make_float2(c[2] + hb, c[3] + hb);
        }
    }
}

// ---------------- kernel 4a: per-column online softmax, 4-way row split, float4 cols ----
// z = mat*4 + part. Each thread owns 4 columns; ty strides rows within the part.
__global__ void col_softmax_part(const float* __restrict__ mask1,
                                 const float* __restrict__ mask2)
{
    const int z    = blockIdx.z;
    const int mat  = z >> 2;
    const int part = z & 3;
    const float* A     = mat ? g_A2  : g_A1;
    const float* rmask = mat ? mask2 : mask1;

    const int b  = blockIdx.y;
    const int tx = threadIdx.x, ty = threadIdx.y;
    const int c0 = blockIdx.x * 128 + tx * 4;
    const float* Ab = A + (size_t)b * LP * LP;

    const int v0 = part * (LEN / 4);
    const int v1 = v0 + (LEN / 4);

    float m[4], d[4], n[4];
#pragma unroll
    for (int j = 0; j < 4; j++) { m[j] = -1e30f; d[j] = 0.f; n[j] = 0.f; }

    for (int v = v0 + ty; v < v1; v += 8) {
        const float4 x4 = *(const float4*)&Ab[(size_t)v * LP + c0];
        const float w = rmask[b * LEN + v];
        const float xs[4] = {x4.x, x4.y, x4.z, x4.w};
#pragma unroll
        for (int j = 0; j < 4; j++) {
            const float x = xs[j];
            if (x > m[j]) {
                const float c = __expf(m[j] - x);
                d[j] = d[j] * c + 1.f;
                n[j] = n[j] * c + w;
                m[j] = x;
            } else {
                const float e = __expf(x - m[j]);
                d[j] += e;
                n[j] += w * e;
            }
        }
    }

    __shared__ float sm[8][32][4], sd[8][32][4], sn[8][32][4];
#pragma unroll
    for (int j = 0; j < 4; j++) { sm[ty][tx][j] = m[j]; sd[ty][tx][j] = d[j]; sn[ty][tx][j] = n[j]; }
    __syncthreads();
    if (ty == 0) {
#pragma unroll
        for (int j = 0; j < 4; j++) {
            float M = sm[0][tx][j], D = sd[0][tx][j], N = sn[0][tx][j];
#pragma unroll
            for (int i = 1; i < 8; i++) {
                const float mi = sm[i][tx][j];
                const float nm = fmaxf(M, mi);
                const float c1 = __expf(M - nm), c2 = __expf(mi - nm);
                D = D * c1 + sd[i][tx][j] * c2;
                N = N * c1 + sn[i][tx][j] * c2;
                M = nm;
            }
            m[j] = M; d[j] = D; n[j] = N;
        }
        const size_t base = ((size_t)z * NB + b) * LP + c0;
        *(float4*)&g_redM[base] = make_float4(m[0], m[1], m[2], m[3]);
        *(float4*)&g_redD[base] = make_float4(d[0], d[1], d[2], d[3]);
        *(float4*)&g_redN[base] = make_float4(n[0], n[1], n[2], n[3]);
    }
}

// ---------------- kernel 4b: merge 4 row-part triples -> w1/w2 ----------------
__global__ void col_merge(const float* __restrict__ mask1, const float* __restrict__ mask2)
{
    const int mat = blockIdx.z;
    const int b   = blockIdx.y;
    const int q   = blockIdx.x * 256 + threadIdx.x;
    if (q >= LEN) return;
    const float* cmask = mat ? mask1 : mask2;
    float*       wout  = mat ? g_w2  : g_w1;

    float M = -1e30f, D = 0.f, N = 0.f;
#pragma unroll
    for (int p = 0; p < 4; p++) {
        const size_t idx = ((size_t)(mat * 4 + p) * NB + b) * LP + q;
        const float mi = g_redM[idx];
        const float nm = fmaxf(M, mi);
        const float c1 = __expf(M - nm), c2 = __expf(mi - nm);
        D = D * c1 + g_redD[idx] * c2;
        N = N * c1 + g_redN[idx] * c2;
        M = nm;
    }
    wout[b * LEN + q] = cmask[b * LEN + q] * N / D;
}

// ---------------- kernel 5: pooled partial GEMVs (vectorized, 64 q-splits) ----------
__global__ void pooled_partial()
{
    const int b  = blockIdx.x;
    const int sp = blockIdx.y;
    const int k4 = threadIdx.x * 4;
    const int q0 = sp * 32;
    const int q1 = (q0 + 32 < LEN) ? q0 + 32 : LEN;
    const float* P = g_A1Y + (size_t)b * LP * KDIM;
    const float* Q = g_A2X + (size_t)b * LP * KDIM;

    float4 acc = make_float4(0.f, 0.f, 0.f, 0.f);
    for (int q = q0; q < q1; q++) {
        const float w1 = g_w1[b * LEN + q];
        const float w2 = g_w2[b * LEN + q];
        const float4 p4 = *(const float4*)&P[(size_t)q * KDIM + k4];
        const float4 q4 = *(const float4*)&Q[(size_t)q * KDIM + k4];
        acc.x += w1 * p4.x + w2 * q4.x;
        acc.y += w1 * p4.y + w2 * q4.y;
        acc.z += w1 * p4.z + w2 * q4.z;
        acc.w += w1 * p4.w + w2 * q4.w;
    }
    *(float4*)&g_part[((size_t)sp * NB + b) * KDIM + k4] = acc;
}

// ---------------- kernel 6: batch layernorm over B=4 ----------------
__global__ void ln_kernel(const float* __restrict__ gamma, const float* __restrict__ beta,
                          float* __restrict__ out)
{
    const int k = blockIdx.x * 256 + threadIdx.x;
    float p[NB];
#pragma unroll
    for (int b = 0; b < NB; b++) {
        float s = 0.f;
#pragma unroll 8
        for (int sp = 0; sp < QSPLIT; sp++) s += g_part[((size_t)sp * NB + b) * KDIM + k];
        p[b] = s * (1.0f / LEN);
    }
    float mu = 0.25f * (p[0] + p[1] + p[2] + p[3]);
    float var = 0.f;
#pragma unroll
    for (int b = 0; b < NB; b++) { float d = p[b] - mu; var += d * d; }
    var *= 0.25f;
    float inv = rsqrtf(var + 1e-5f);
#pragma unroll
    for (int b = 0; b < NB; b++)
        out[b * KDIM + k] = gamma[k] * (p[b] - mu) * inv + beta[k];
}

// ---------------- launch ----------------
extern "C" void kernel_launch(void* const* d_in, const int* in_sizes, int n_in,
                              void* d_out, int out_size)
{
    const float* X      = (const float*)d_in[0];
    const float* Y      = (const float*)d_in[1];
    const float* mask1  = (const float*)d_in[2];
    const float* mask2  = (const float*)d_in[3];
    const float* Qv     = (const float*)d_in[4];
    const float* Qg     = (const float*)d_in[5];
    const float* Qb     = (const float*)d_in[6];
    const float* Kv     = (const float*)d_in[7];
    const float* Kg     = (const float*)d_in[8];
    const float* Kb     = (const float*)d_in[9];
    const float* h_mat  = (const float*)d_in[10];
    const float* h_bias = (const float*)d_in[11];
    const float* gamma  = (const float*)d_in[12];
    const float* beta   = (const float*)d_in[13];
    float* out = (float*)d_out;

    static bool attr_done = false;
    if (!attr_done) {
        cudaFuncSetAttribute(fc_mma,  cudaFuncAttributeMaxDynamicSharedMemorySize, SMEM_BYTES);
        cudaFuncSetAttribute(att_mma, cudaFuncAttributeMaxDynamicSharedMemorySize, SMEM_BYTES);
        attr_done = true;
    }

    norm_kernel<<<2, 256>>>(Qv, Qg, Kv, Kg);

    dim3 fcGrid(KDIM / 128, (NB * LP) / 128, 4);
    fc_mma<<<fcGrid, 256, SMEM_BYTES>>>(X, Y, Qv, Kv, Qb, Kb, h_mat);

    dim3 attGrid(LP / 128, LP / 128, NB * 2);
    att_mma<<<attGrid, 256, SMEM_BYTES>>>(h_bias);

    col_softmax_part<<<dim3(LP / 128, NB, 8), dim3(32, 8)>>>(mask1, mask2);
    col_merge<<<dim3((LEN + 255) / 256, NB, 2), 256>>>(mask1, mask2);

    pooled_partial<<<dim3(NB, QSPLIT), 128>>>();
    ln_kernel<<<KDIM / 256, 256>>>(gamma, beta, out);
}